// round 1
// baseline (speedup 1.0000x reference)
#include <cuda_runtime.h>
#include <math.h>

#define FULLMASK 0xffffffffu

// Problem constants
#define BB 8
#define SS 1024
#define EE 512
#define HH 8
#define DD 64

// ---------------- scratch (device globals: allocation-free) ----------------
__device__ float g_qh[BB * HH * SS * DD];   // [b][h][s][d]
__device__ float g_kh[BB * HH * SS * DD];
__device__ float g_vh[BB * HH * SS * DD];
__device__ float g_ao[BB * SS * EE];        // attention output, [b][s][h*64+d]

// ---------------- SGEMM: C = A @ W^T + bias -------------------------------
// A [8192,512] row-major, W [512,512] row-major (K-contiguous both).
// BM=BN=128, BK=8, 256 threads, 8x8 per-thread tile.
// src_sel: 0 -> use A_param, 1 -> use g_ao
// dst_mode: 0/1/2 -> write remapped [B,H,S,D] into g_qh/g_kh/g_vh; 3 -> C_param[m*512+n]
__global__ __launch_bounds__(256, 2)
void sgemm_nt(const float* __restrict__ A_param, const float* __restrict__ W,
              const float* __restrict__ bias, float* __restrict__ C_param,
              int src_sel, int dst_mode)
{
    __shared__ float As[8][128];
    __shared__ float Bs[8][128];

    const float* A = src_sel ? (const float*)g_ao : A_param;

    const int tid = threadIdx.x;
    const int m0 = blockIdx.x * 128;
    const int n0 = blockIdx.y * 128;
    const int ty = tid >> 4;        // 0..15
    const int tx = tid & 15;        // 0..15
    const int lr = tid >> 1;        // 0..127 (tile row for loads)
    const int lc = (tid & 1) << 2;  // 0 or 4 (k-offset for loads)

    const float* Ap = A + (m0 + lr) * 512 + lc;
    const float* Wp = W + (n0 + lr) * 512 + lc;

    float acc[8][8];
#pragma unroll
    for (int i = 0; i < 8; i++)
#pragma unroll
        for (int j = 0; j < 8; j++) acc[i][j] = 0.f;

    for (int k0 = 0; k0 < 512; k0 += 8) {
        float4 av = *(const float4*)(Ap + k0);
        float4 wv = *(const float4*)(Wp + k0);
        __syncthreads();
        As[lc + 0][lr] = av.x; As[lc + 1][lr] = av.y;
        As[lc + 2][lr] = av.z; As[lc + 3][lr] = av.w;
        Bs[lc + 0][lr] = wv.x; Bs[lc + 1][lr] = wv.y;
        Bs[lc + 2][lr] = wv.z; Bs[lc + 3][lr] = wv.w;
        __syncthreads();
#pragma unroll
        for (int kk = 0; kk < 8; kk++) {
            float a[8], bb[8];
            *(float4*)(a)      = *(const float4*)&As[kk][ty * 8];
            *(float4*)(a + 4)  = *(const float4*)&As[kk][ty * 8 + 4];
            *(float4*)(bb)     = *(const float4*)&Bs[kk][tx * 8];
            *(float4*)(bb + 4) = *(const float4*)&Bs[kk][tx * 8 + 4];
#pragma unroll
            for (int i = 0; i < 8; i++)
#pragma unroll
                for (int j = 0; j < 8; j++)
                    acc[i][j] = fmaf(a[i], bb[j], acc[i][j]);
        }
    }

#pragma unroll
    for (int i = 0; i < 8; i++) {
        const int m = m0 + ty * 8 + i;
#pragma unroll
        for (int j = 0; j < 8; j++) {
            const int n = n0 + tx * 8 + j;
            const float v = acc[i][j] + bias[n];
            if (dst_mode < 3) {
                // remap (m, n) -> [b][h][s][d]
                const int b = m >> 10, s = m & 1023, h = n >> 6, d = n & 63;
                const int idx = (((b << 3) + h) * 1024 + s) * 64 + d;
                if (dst_mode == 0)      g_qh[idx] = v;
                else if (dst_mode == 1) g_kh[idx] = v;
                else                    g_vh[idx] = v;
            } else {
                C_param[m * 512 + n] = v;
            }
        }
    }
}

// ---------------- fused decay-attention ------------------------------------
__device__ __forceinline__ float wredmax(float v) {
#pragma unroll
    for (int o = 16; o; o >>= 1) v = fmaxf(v, __shfl_xor_sync(FULLMASK, v, o));
    return v;
}
__device__ __forceinline__ float wredsum(float v) {
#pragma unroll
    for (int o = 16; o; o >>= 1) v += __shfl_xor_sync(FULLMASK, v, o);
    return v;
}

// grid (128, H, B), 256 threads (8 warps, 1 query row/warp)
__global__ __launch_bounds__(256, 2)
void attn_kernel(const float* __restrict__ gammas)
{
    const int tid = threadIdx.x, lane = tid & 31, w = tid >> 5;
    const int bx = blockIdx.x, h = blockIdx.y, b = blockIdx.z;
    const int i = bx * 8 + w;                       // query row
    const int ntiles = (8 * bx + 135) >> 7;         // key tiles of 128 needed
    const int bh = (b * 8 + h) * (1024 * 64);
    const float* qb = g_qh + bh;
    const float* kb = g_kh + bh;
    const float* vb = g_vh + bh;

    __shared__ float qs[8][64];
    __shared__ __align__(16) float sbuf[64 * 129];  // K (transposed, padded) / V (raw) union

    if (tid < 128) {
        const int r = tid >> 4, d4 = (tid & 15) << 2;
        *(float4*)&qs[r][d4] = *(const float4*)&qb[(bx * 8 + r) * 64 + d4];
    }

    const float gx = gammas[h];
    const float gamma = -((gx > 20.f) ? gx : log1pf(expf(gx)));  // -softplus

    float sreg[32];
#pragma unroll
    for (int c = 0; c < 32; c++) sreg[c] = 0.f;

    __syncthreads();

    // ---- Phase 1: scores (QK^T), row in registers (j = c/4*128 + (c&3)*32 + lane)
    for (int kt = 0; kt < ntiles; kt++) {
#pragma unroll
        for (int r = 0; r < 8; r++) {
            const int fi = tid + r * 256;
            const int jj = fi >> 4, d4 = (fi & 15) << 2;
            const float4 kv = *(const float4*)&kb[(kt * 128 + jj) * 64 + d4];
            sbuf[(d4 + 0) * 129 + jj] = kv.x;
            sbuf[(d4 + 1) * 129 + jj] = kv.y;
            sbuf[(d4 + 2) * 129 + jj] = kv.z;
            sbuf[(d4 + 3) * 129 + jj] = kv.w;
        }
        __syncthreads();
        float a0 = 0.f, a1 = 0.f, a2 = 0.f, a3 = 0.f;
#pragma unroll 8
        for (int d = 0; d < 64; d++) {
            const float qd = qs[w][d];
            const float* kp = &sbuf[d * 129 + lane];
            a0 = fmaf(qd, kp[0],  a0);
            a1 = fmaf(qd, kp[32], a1);
            a2 = fmaf(qd, kp[64], a2);
            a3 = fmaf(qd, kp[96], a3);
        }
        __syncthreads();
        switch (kt) {
            case 0: sreg[0]=a0;  sreg[1]=a1;  sreg[2]=a2;  sreg[3]=a3;  break;
            case 1: sreg[4]=a0;  sreg[5]=a1;  sreg[6]=a2;  sreg[7]=a3;  break;
            case 2: sreg[8]=a0;  sreg[9]=a1;  sreg[10]=a2; sreg[11]=a3; break;
            case 3: sreg[12]=a0; sreg[13]=a1; sreg[14]=a2; sreg[15]=a3; break;
            case 4: sreg[16]=a0; sreg[17]=a1; sreg[18]=a2; sreg[19]=a3; break;
            case 5: sreg[20]=a0; sreg[21]=a1; sreg[22]=a2; sreg[23]=a3; break;
            case 6: sreg[24]=a0; sreg[25]=a1; sreg[26]=a2; sreg[27]=a3; break;
            default:sreg[28]=a0; sreg[29]=a1; sreg[30]=a2; sreg[31]=a3; break;
        }
    }

    // ---- Phase 2: softmax -> cumsum decay -> rescaled softmax (all registers)
    const int nreg = ntiles * 4;

    float m1 = -3.0e38f;
#pragma unroll
    for (int c = 0; c < 32; c++) if (c < nreg) {
        const int j = (c >> 2) * 128 + (c & 3) * 32 + lane;
        sreg[c] *= 0.125f;                           // 1/sqrt(64)
        if (j <= i) m1 = fmaxf(m1, sreg[c]);
    }
    m1 = wredmax(m1);

    float p[32];
    float Z = 0.f;
#pragma unroll
    for (int c = 0; c < 32; c++) {
        p[c] = 0.f;
        if (c < nreg) {
            const int j = (c >> 2) * 128 + (c & 3) * 32 + lane;
            if (j <= i) p[c] = expf(sreg[c] - m1);
            Z += p[c];
        }
    }
    Z = wredsum(Z);
    const float invZ = 1.f / Z;

    float T = 0.f;
#pragma unroll
    for (int c = 0; c < 32; c++) if (c < nreg) { p[c] *= invZ; T += p[c]; }
    T = wredsum(T);                                  // == disttot

    float carry = 0.f;
#pragma unroll
    for (int c = 0; c < 32; c++) if (c < nreg) {
        float v = p[c];
#pragma unroll
        for (int o = 1; o < 32; o <<= 1) {           // inclusive warp scan
            const float n = __shfl_up_sync(FULLMASK, v, o);
            if (lane >= o) v += n;
        }
        const float cum = carry + v;
        const float nc = __shfl_sync(FULLMASK, cum, 31);
        const int j = (c >> 2) * 128 + (c & 3) * 32 + lane;
        float x = (T - cum) * (float)(i - j);
        x = fmaxf(x, 0.f);
        float eff = expf(sqrtf(x) * gamma);
        eff = fminf(fmaxf(eff, 1e-5f), 1e5f);        // clip like reference
        sreg[c] *= eff;
        carry = nc;
    }

    float m2 = -3.0e38f;
#pragma unroll
    for (int c = 0; c < 32; c++) if (c < nreg) {
        const int j = (c >> 2) * 128 + (c & 3) * 32 + lane;
        if (j <= i) m2 = fmaxf(m2, sreg[c]);
    }
    m2 = wredmax(m2);

    float Z2 = 0.f;
#pragma unroll
    for (int c = 0; c < 32; c++) if (c < nreg) {
        const int j = (c >> 2) * 128 + (c & 3) * 32 + lane;
        sreg[c] = (j <= i) ? expf(sreg[c] - m2) : 0.f;
        Z2 += sreg[c];
    }
    Z2 = wredsum(Z2);
    const float psc = (i == 0) ? 0.f : (1.f / Z2);   // zero_pad first query row
#pragma unroll
    for (int c = 0; c < 32; c++) sreg[c] *= psc;

    // ---- Phase 3: P @ V (lane owns output dims 2*lane, 2*lane+1)
    float o0 = 0.f, o1 = 0.f;
    for (int kt = 0; kt < ntiles; kt++) {
        __syncthreads();
#pragma unroll
        for (int r = 0; r < 8; r++) {
            const int fi = tid + r * 256;
            const int jj = fi >> 4, d4 = (fi & 15) << 2;
            *(float4*)&sbuf[jj * 64 + d4] =
                *(const float4*)&vb[(kt * 128 + jj) * 64 + d4];
        }
        __syncthreads();
        float rr[4];
        switch (kt) {
            case 0: rr[0]=sreg[0];  rr[1]=sreg[1];  rr[2]=sreg[2];  rr[3]=sreg[3];  break;
            case 1: rr[0]=sreg[4];  rr[1]=sreg[5];  rr[2]=sreg[6];  rr[3]=sreg[7];  break;
            case 2: rr[0]=sreg[8];  rr[1]=sreg[9];  rr[2]=sreg[10]; rr[3]=sreg[11]; break;
            case 3: rr[0]=sreg[12]; rr[1]=sreg[13]; rr[2]=sreg[14]; rr[3]=sreg[15]; break;
            case 4: rr[0]=sreg[16]; rr[1]=sreg[17]; rr[2]=sreg[18]; rr[3]=sreg[19]; break;
            case 5: rr[0]=sreg[20]; rr[1]=sreg[21]; rr[2]=sreg[22]; rr[3]=sreg[23]; break;
            case 6: rr[0]=sreg[24]; rr[1]=sreg[25]; rr[2]=sreg[26]; rr[3]=sreg[27]; break;
            default:rr[0]=sreg[28]; rr[1]=sreg[29]; rr[2]=sreg[30]; rr[3]=sreg[31]; break;
        }
#pragma unroll
        for (int t = 0; t < 4; t++) {
            const float pr = rr[t];
            for (int src = 0; src < 32; src++) {
                const float pj = __shfl_sync(FULLMASK, pr, src);   // warp-uniform
                if (pj != 0.f) {
                    const float2 vv =
                        *(const float2*)&sbuf[(t * 32 + src) * 64 + (lane << 1)];
                    o0 = fmaf(pj, vv.x, o0);
                    o1 = fmaf(pj, vv.y, o1);
                }
            }
        }
    }

    *(float2*)&g_ao[(b * 1024 + i) * 512 + h * 64 + (lane << 1)] =
        make_float2(o0, o1);
}

// ---------------- launch ----------------------------------------------------
extern "C" void kernel_launch(void* const* d_in, const int* in_sizes, int n_in,
                              void* d_out, int out_size)
{
    (void)in_sizes; (void)n_in; (void)out_size;
    const float* q  = (const float*)d_in[0];
    const float* k  = (const float*)d_in[1];
    const float* v  = (const float*)d_in[2];
    const float* Wk = (const float*)d_in[3];
    const float* bk = (const float*)d_in[4];
    const float* Wv = (const float*)d_in[5];
    const float* bv = (const float*)d_in[6];
    const float* Wo = (const float*)d_in[7];
    const float* bo = (const float*)d_in[8];
    const float* gm = (const float*)d_in[9];
    float* out = (float*)d_out;

    const dim3 ggrid(64, 4);   // M/128 x N/128
    sgemm_nt<<<ggrid, 256>>>(q, Wk, bk, nullptr, 0, 0);   // -> g_qh
    sgemm_nt<<<ggrid, 256>>>(k, Wk, bk, nullptr, 0, 1);   // -> g_kh
    sgemm_nt<<<ggrid, 256>>>(v, Wv, bv, nullptr, 0, 2);   // -> g_vh

    attn_kernel<<<dim3(128, 8, 8), 256>>>(gm);            // -> g_ao

    sgemm_nt<<<ggrid, 256>>>(nullptr, Wo, bo, out, 1, 3); // g_ao -> d_out
}

// round 3
// speedup vs baseline: 1.1974x; 1.1974x over previous
#include <cuda_runtime.h>
#include <math.h>

#define FULLMASK 0xffffffffu

#define BB 8
#define SS 1024
#define EE 512
#define HH 8
#define DD 64

// ---------------- scratch (device globals: allocation-free) ----------------
__device__ float g_qh[BB * HH * SS * DD];   // [b][h][s][d]
__device__ float g_kh[BB * HH * SS * DD];
__device__ float g_vh[BB * HH * SS * DD];
__device__ float g_ao[BB * SS * EE];        // attention output, [b][s][h*64+d]

// ---------------- SGEMM: C = A @ W^T + bias -------------------------------
// mode 0: fused QK projection. grid.x = 128: bx<64 -> A(q)->g_qh, bx>=64 -> A2(k)->g_kh
// mode 2: V projection -> g_vh (grid.x = 64)
// mode 3: output projection: g_ao @ Wo^T + bo -> C (grid.x = 64)
__global__ __launch_bounds__(256, 2)
void sgemm_nt(const float* __restrict__ A_param, const float* __restrict__ A2_param,
              const float* __restrict__ W, const float* __restrict__ bias,
              float* __restrict__ C_param, int mode)
{
    __shared__ float As[8][128];
    __shared__ float Bs[8][128];

    int bxm = blockIdx.x;
    const float* A;
    float* dst_qkv = nullptr;
    if (mode == 0) {
        if (bxm < 64) { A = A_param; dst_qkv = g_qh; }
        else          { A = A2_param; dst_qkv = g_kh; bxm -= 64; }
    } else if (mode == 2) {
        A = A_param; dst_qkv = g_vh;
    } else {
        A = (const float*)g_ao;
    }

    const int tid = threadIdx.x;
    const int m0 = bxm * 128;
    const int n0 = blockIdx.y * 128;
    const int ty = tid >> 4;        // 0..15
    const int tx = tid & 15;        // 0..15
    const int lr = tid >> 1;        // 0..127
    const int lc = (tid & 1) << 2;  // 0 or 4

    const float* Ap = A + (m0 + lr) * 512 + lc;
    const float* Wp = W + (n0 + lr) * 512 + lc;

    float acc[8][8];
#pragma unroll
    for (int i = 0; i < 8; i++)
#pragma unroll
        for (int j = 0; j < 8; j++) acc[i][j] = 0.f;

    for (int k0 = 0; k0 < 512; k0 += 8) {
        float4 av = *(const float4*)(Ap + k0);
        float4 wv = *(const float4*)(Wp + k0);
        __syncthreads();
        As[lc + 0][lr] = av.x; As[lc + 1][lr] = av.y;
        As[lc + 2][lr] = av.z; As[lc + 3][lr] = av.w;
        Bs[lc + 0][lr] = wv.x; Bs[lc + 1][lr] = wv.y;
        Bs[lc + 2][lr] = wv.z; Bs[lc + 3][lr] = wv.w;
        __syncthreads();
#pragma unroll
        for (int kk = 0; kk < 8; kk++) {
            float a[8], bb[8];
            *(float4*)(a)      = *(const float4*)&As[kk][ty * 8];
            *(float4*)(a + 4)  = *(const float4*)&As[kk][ty * 8 + 4];
            *(float4*)(bb)     = *(const float4*)&Bs[kk][tx * 8];
            *(float4*)(bb + 4) = *(const float4*)&Bs[kk][tx * 8 + 4];
#pragma unroll
            for (int i = 0; i < 8; i++)
#pragma unroll
                for (int j = 0; j < 8; j++)
                    acc[i][j] = fmaf(a[i], bb[j], acc[i][j]);
        }
    }

#pragma unroll
    for (int i = 0; i < 8; i++) {
        const int m = m0 + ty * 8 + i;
#pragma unroll
        for (int j = 0; j < 8; j++) {
            const int n = n0 + tx * 8 + j;
            const float v = acc[i][j] + bias[n];
            if (mode == 3) {
                C_param[m * 512 + n] = v;
            } else {
                const int b = m >> 10, s = m & 1023, hh = n >> 6, d = n & 63;
                dst_qkv[(((b << 3) + hh) * 1024 + s) * 64 + d] = v;
            }
        }
    }
}

// ---------------- fused decay-attention ------------------------------------
__device__ __forceinline__ float wredmax(float v) {
#pragma unroll
    for (int o = 16; o; o >>= 1) v = fmaxf(v, __shfl_xor_sync(FULLMASK, v, o));
    return v;
}
__device__ __forceinline__ float wredsum(float v) {
#pragma unroll
    for (int o = 16; o; o >>= 1) v += __shfl_xor_sync(FULLMASK, v, o);
    return v;
}

// softmax -> cumsum decay -> rescaled softmax, entirely in registers.
// s[] holds raw scores on entry (j = (c>>2)*128 + (c&3)*32 + lane),
// final (normalized, decay-adjusted, row-0-zeroed) probabilities on exit.
__device__ __forceinline__ void row_decay_softmax(float (&s)[32], const int i,
                                                  const int nreg, const int lane,
                                                  const float gamma)
{
    float m1 = -3.0e38f;
#pragma unroll
    for (int c = 0; c < 32; c++) if (c < nreg) {
        const int j = (c >> 2) * 128 + (c & 3) * 32 + lane;
        s[c] *= 0.125f;                              // 1/sqrt(64)
        if (j <= i) m1 = fmaxf(m1, s[c]);
    }
    m1 = wredmax(m1);

    float Z = 0.f;
#pragma unroll
    for (int c = 0; c < 32; c++) if (c < nreg) {
        const int j = (c >> 2) * 128 + (c & 3) * 32 + lane;
        if (j <= i) Z += expf(s[c] - m1);
    }
    Z = wredsum(Z);
    const float invZ = 1.f / Z;

    // scan pass: cumsum of normalized probs; disttot == 1 exactly.
    float carry = 0.f;
#pragma unroll
    for (int c = 0; c < 32; c++) if (c < nreg) {
        const int j = (c >> 2) * 128 + (c & 3) * 32 + lane;
        float v = (j <= i) ? expf(s[c] - m1) * invZ : 0.f;
#pragma unroll
        for (int o = 1; o < 32; o <<= 1) {
            const float n = __shfl_up_sync(FULLMASK, v, o);
            if (lane >= o) v += n;
        }
        const float cum = carry + v;
        carry = __shfl_sync(FULLMASK, cum, 31);
        float x = fmaxf((1.f - cum) * (float)(i - j), 0.f);
        float eff = expf(sqrtf(x) * gamma);
        eff = fminf(fmaxf(eff, 1e-5f), 1e5f);
        s[c] *= eff;
    }

    float m2 = -3.0e38f;
#pragma unroll
    for (int c = 0; c < 32; c++) if (c < nreg) {
        const int j = (c >> 2) * 128 + (c & 3) * 32 + lane;
        if (j <= i) m2 = fmaxf(m2, s[c]);
    }
    m2 = wredmax(m2);

    float Z2 = 0.f;
#pragma unroll
    for (int c = 0; c < 32; c++) {
        if (c < nreg) {
            const int j = (c >> 2) * 128 + (c & 3) * 32 + lane;
            s[c] = (j <= i) ? expf(s[c] - m2) : 0.f;
            Z2 += s[c];
        } else s[c] = 0.f;
    }
    Z2 = wredsum(Z2);
    const float psc = (i == 0) ? 0.f : (1.f / Z2);   // zero_pad first query row
#pragma unroll
    for (int c = 0; c < 32; c++) s[c] *= psc;
}

// grid (64, H, B), 256 threads: 8 warps x 2 query rows each = 16 rows/block
__global__ __launch_bounds__(256, 2)
void attn_kernel(const float* __restrict__ gammas)
{
    const int tid = threadIdx.x, lane = tid & 31, w = tid >> 5;
    const int bx = blockIdx.x, h = blockIdx.y, b = blockIdx.z;
    const int r0 = bx * 16 + 2 * w;                  // this warp's query rows
    const int r1 = r0 + 1;
    const int ntiles = (bx * 16 + 143) >> 7;         // key tiles of 128 needed
    const int bh = (b * 8 + h) * (1024 * 64);
    const float* qb = g_qh + bh;
    const float* kb = g_kh + bh;
    const float* vb = g_vh + bh;

    __shared__ float qs[16][64];
    __shared__ __align__(16) float sbuf[64 * 129];   // K^T (padded) / V (raw) union

    {
        const int r = tid >> 4, d4 = (tid & 15) << 2;
        *(float4*)&qs[r][d4] = *(const float4*)&qb[(bx * 16 + r) * 64 + d4];
    }

    const float gx = gammas[h];
    const float gamma = -((gx > 20.f) ? gx : log1pf(expf(gx)));  // -softplus

    float s0[32], s1[32];
    const float* q0row = &qs[2 * w][0];
    const float* q1row = &qs[2 * w + 1][0];

    // ---- Phase 1: scores (QK^T); row j-map: j = (c>>2)*128 + (c&3)*32 + lane
#pragma unroll
    for (int kt = 0; kt < 8; kt++) {
        if (kt < ntiles) {
            float4 kv[8];
#pragma unroll
            for (int r = 0; r < 8; r++) {
                const int fi = tid + r * 256;
                const int jj = fi >> 4, d4 = (fi & 15) << 2;
                kv[r] = *(const float4*)&kb[(kt * 128 + jj) * 64 + d4];
            }
            __syncthreads();
#pragma unroll
            for (int r = 0; r < 8; r++) {
                const int fi = tid + r * 256;
                const int jj = fi >> 4, d4 = (fi & 15) << 2;
                sbuf[(d4 + 0) * 129 + jj] = kv[r].x;
                sbuf[(d4 + 1) * 129 + jj] = kv[r].y;
                sbuf[(d4 + 2) * 129 + jj] = kv[r].z;
                sbuf[(d4 + 3) * 129 + jj] = kv[r].w;
            }
            __syncthreads();
            float a00 = 0.f, a01 = 0.f, a02 = 0.f, a03 = 0.f;
            float a10 = 0.f, a11 = 0.f, a12 = 0.f, a13 = 0.f;
#pragma unroll 8
            for (int d = 0; d < 64; d++) {
                const float q0 = q0row[d];
                const float q1 = q1row[d];
                const float* kp = &sbuf[d * 129 + lane];
                const float k0 = kp[0], k1 = kp[32], k2 = kp[64], k3 = kp[96];
                a00 = fmaf(q0, k0, a00); a01 = fmaf(q0, k1, a01);
                a02 = fmaf(q0, k2, a02); a03 = fmaf(q0, k3, a03);
                a10 = fmaf(q1, k0, a10); a11 = fmaf(q1, k1, a11);
                a12 = fmaf(q1, k2, a12); a13 = fmaf(q1, k3, a13);
            }
            __syncthreads();
            s0[kt * 4 + 0] = a00; s0[kt * 4 + 1] = a01;
            s0[kt * 4 + 2] = a02; s0[kt * 4 + 3] = a03;
            s1[kt * 4 + 0] = a10; s1[kt * 4 + 1] = a11;
            s1[kt * 4 + 2] = a12; s1[kt * 4 + 3] = a13;
        }
    }

    // ---- Phase 2: per-row softmax/decay/softmax
    const int nreg = ntiles * 4;
    row_decay_softmax(s0, r0, nreg, lane, gamma);
    row_decay_softmax(s1, r1, nreg, lane, gamma);

    // ---- Phase 3: P @ V (lane owns output dims 2*lane, 2*lane+1)
    float o00 = 0.f, o01 = 0.f, o10 = 0.f, o11 = 0.f;
#pragma unroll
    for (int kt = 0; kt < 8; kt++) {
        if (kt < ntiles) {
            float4 vv4[8];
#pragma unroll
            for (int r = 0; r < 8; r++) {
                const int fi = tid + r * 256;
                const int jj = fi >> 4, d4 = (fi & 15) << 2;
                vv4[r] = *(const float4*)&vb[(kt * 128 + jj) * 64 + d4];
            }
            __syncthreads();
#pragma unroll
            for (int r = 0; r < 8; r++) {
                const int fi = tid + r * 256;
                const int jj = fi >> 4, d4 = (fi & 15) << 2;
                *(float4*)&sbuf[jj * 64 + d4] = vv4[r];
            }
            __syncthreads();
#pragma unroll
            for (int t = 0; t < 4; t++) {
                const float pr0 = s0[kt * 4 + t];
                const float pr1 = s1[kt * 4 + t];
                for (int src = 0; src < 32; src++) {
                    const float pj0 = __shfl_sync(FULLMASK, pr0, src);
                    const float pj1 = __shfl_sync(FULLMASK, pr1, src);
                    if (pj0 != 0.f || pj1 != 0.f) {     // warp-uniform skip
                        const float2 vv =
                            *(const float2*)&sbuf[(t * 32 + src) * 64 + (lane << 1)];
                        o00 = fmaf(pj0, vv.x, o00); o01 = fmaf(pj0, vv.y, o01);
                        o10 = fmaf(pj1, vv.x, o10); o11 = fmaf(pj1, vv.y, o11);
                    }
                }
            }
        }
    }

    *(float2*)&g_ao[(b * 1024 + r0) * 512 + h * 64 + (lane << 1)] =
        make_float2(o00, o01);
    *(float2*)&g_ao[(b * 1024 + r1) * 512 + h * 64 + (lane << 1)] =
        make_float2(o10, o11);
}

// ---------------- launch ----------------------------------------------------
extern "C" void kernel_launch(void* const* d_in, const int* in_sizes, int n_in,
                              void* d_out, int out_size)
{
    (void)in_sizes; (void)n_in; (void)out_size;
    const float* q  = (const float*)d_in[0];
    const float* k  = (const float*)d_in[1];
    const float* v  = (const float*)d_in[2];
    const float* Wk = (const float*)d_in[3];
    const float* bk = (const float*)d_in[4];
    const float* Wv = (const float*)d_in[5];
    const float* bv = (const float*)d_in[6];
    const float* Wo = (const float*)d_in[7];
    const float* bo = (const float*)d_in[8];
    const float* gm = (const float*)d_in[9];
    float* out = (float*)d_out;

    sgemm_nt<<<dim3(128, 4), 256>>>(q, k, Wk, bk, nullptr, 0);       // q,k -> g_qh,g_kh
    sgemm_nt<<<dim3(64, 4), 256>>>(v, nullptr, Wv, bv, nullptr, 2);  // -> g_vh

    attn_kernel<<<dim3(64, 8, 8), 256>>>(gm);                        // -> g_ao

    sgemm_nt<<<dim3(64, 4), 256>>>(nullptr, nullptr, Wo, bo, out, 3); // -> d_out
}

// round 4
// speedup vs baseline: 1.3213x; 1.1035x over previous
#include <cuda_runtime.h>
#include <math.h>
#include <mma.h>

using namespace nvcuda;

#define FULLMASK 0xffffffffu

#define BB 8
#define SS 1024
#define EE 512
#define HH 8
#define DD 64

// ---------------- scratch (device globals: allocation-free) ----------------
__device__ float g_qh[BB * HH * SS * DD];   // [b][h][s][d]
__device__ float g_kh[BB * HH * SS * DD];
__device__ float g_vh[BB * HH * SS * DD];
__device__ float g_ao[BB * SS * EE];        // attention output, [b][s][h*64+d]

// ---------------- SGEMM: C = A @ W^T + bias (unchanged, proven) ------------
__global__ __launch_bounds__(256, 2)
void sgemm_nt(const float* __restrict__ A_param, const float* __restrict__ A2_param,
              const float* __restrict__ W, const float* __restrict__ bias,
              float* __restrict__ C_param, int mode)
{
    __shared__ float As[8][128];
    __shared__ float Bs[8][128];

    int bxm = blockIdx.x;
    const float* A;
    float* dst_qkv = nullptr;
    if (mode == 0) {
        if (bxm < 64) { A = A_param; dst_qkv = g_qh; }
        else          { A = A2_param; dst_qkv = g_kh; bxm -= 64; }
    } else if (mode == 2) {
        A = A_param; dst_qkv = g_vh;
    } else {
        A = (const float*)g_ao;
    }

    const int tid = threadIdx.x;
    const int m0 = bxm * 128;
    const int n0 = blockIdx.y * 128;
    const int ty = tid >> 4;
    const int tx = tid & 15;
    const int lr = tid >> 1;
    const int lc = (tid & 1) << 2;

    const float* Ap = A + (m0 + lr) * 512 + lc;
    const float* Wp = W + (n0 + lr) * 512 + lc;

    float acc[8][8];
#pragma unroll
    for (int i = 0; i < 8; i++)
#pragma unroll
        for (int j = 0; j < 8; j++) acc[i][j] = 0.f;

    for (int k0 = 0; k0 < 512; k0 += 8) {
        float4 av = *(const float4*)(Ap + k0);
        float4 wv = *(const float4*)(Wp + k0);
        __syncthreads();
        As[lc + 0][lr] = av.x; As[lc + 1][lr] = av.y;
        As[lc + 2][lr] = av.z; As[lc + 3][lr] = av.w;
        Bs[lc + 0][lr] = wv.x; Bs[lc + 1][lr] = wv.y;
        Bs[lc + 2][lr] = wv.z; Bs[lc + 3][lr] = wv.w;
        __syncthreads();
#pragma unroll
        for (int kk = 0; kk < 8; kk++) {
            float a[8], bb[8];
            *(float4*)(a)      = *(const float4*)&As[kk][ty * 8];
            *(float4*)(a + 4)  = *(const float4*)&As[kk][ty * 8 + 4];
            *(float4*)(bb)     = *(const float4*)&Bs[kk][tx * 8];
            *(float4*)(bb + 4) = *(const float4*)&Bs[kk][tx * 8 + 4];
#pragma unroll
            for (int i = 0; i < 8; i++)
#pragma unroll
                for (int j = 0; j < 8; j++)
                    acc[i][j] = fmaf(a[i], bb[j], acc[i][j]);
        }
    }

#pragma unroll
    for (int i = 0; i < 8; i++) {
        const int m = m0 + ty * 8 + i;
#pragma unroll
        for (int j = 0; j < 8; j++) {
            const int n = n0 + tx * 8 + j;
            const float v = acc[i][j] + bias[n];
            if (mode == 3) {
                C_param[m * 512 + n] = v;
            } else {
                const int b = m >> 10, s = m & 1023, hh = n >> 6, d = n & 63;
                dst_qkv[(((b << 3) + hh) * 1024 + s) * 64 + d] = v;
            }
        }
    }
}

// ---------------- fused decay-attention ------------------------------------
__device__ __forceinline__ float wredmax(float v) {
#pragma unroll
    for (int o = 16; o; o >>= 1) v = fmaxf(v, __shfl_xor_sync(FULLMASK, v, o));
    return v;
}
__device__ __forceinline__ float wredsum(float v) {
#pragma unroll
    for (int o = 16; o; o >>= 1) v += __shfl_xor_sync(FULLMASK, v, o);
    return v;
}

// softmax -> cumsum decay -> rescaled softmax, entirely in registers.
// j-map: j = (c>>2)*128 + (c&3)*32 + lane
__device__ __forceinline__ void row_decay_softmax(float (&s)[32], const int i,
                                                  const int nreg, const int lane,
                                                  const float gamma)
{
    float m1 = -3.0e38f;
#pragma unroll
    for (int c = 0; c < 32; c++) if (c < nreg) {
        const int j = (c >> 2) * 128 + (c & 3) * 32 + lane;
        s[c] *= 0.125f;                              // 1/sqrt(64)
        if (j <= i) m1 = fmaxf(m1, s[c]);
    }
    m1 = wredmax(m1);

    float Z = 0.f;
#pragma unroll
    for (int c = 0; c < 32; c++) if (c < nreg) {
        const int j = (c >> 2) * 128 + (c & 3) * 32 + lane;
        if (j <= i) Z += expf(s[c] - m1);
    }
    Z = wredsum(Z);
    const float invZ = 1.f / Z;

    float carry = 0.f;
#pragma unroll
    for (int c = 0; c < 32; c++) if (c < nreg) {
        const int j = (c >> 2) * 128 + (c & 3) * 32 + lane;
        float v = (j <= i) ? expf(s[c] - m1) * invZ : 0.f;
#pragma unroll
        for (int o = 1; o < 32; o <<= 1) {
            const float n = __shfl_up_sync(FULLMASK, v, o);
            if (lane >= o) v += n;
        }
        const float cum = carry + v;
        carry = __shfl_sync(FULLMASK, cum, 31);
        float x = fmaxf((1.f - cum) * (float)(i - j), 0.f);
        float eff = expf(sqrtf(x) * gamma);
        eff = fminf(fmaxf(eff, 1e-5f), 1e5f);
        s[c] *= eff;
    }

    float m2 = -3.0e38f;
#pragma unroll
    for (int c = 0; c < 32; c++) if (c < nreg) {
        const int j = (c >> 2) * 128 + (c & 3) * 32 + lane;
        if (j <= i) m2 = fmaxf(m2, s[c]);
    }
    m2 = wredmax(m2);

    float Z2 = 0.f;
#pragma unroll
    for (int c = 0; c < 32; c++) {
        if (c < nreg) {
            const int j = (c >> 2) * 128 + (c & 3) * 32 + lane;
            s[c] = (j <= i) ? expf(s[c] - m2) : 0.f;
            Z2 += s[c];
        } else s[c] = 0.f;
    }
    Z2 = wredsum(Z2);
    const float psc = (i == 0) ? 0.f : (1.f / Z2);
#pragma unroll
    for (int c = 0; c < 32; c++) s[c] *= psc;
}

#define KV_LD 68     // padded leading dim for K/V tile (mult of 4)
#define ST_LD 136    // padded leading dim for stage buffer (mult of 4)

// grid (64, H, B), 256 threads: 8 warps, block covers 16 query rows.
// QK^T and P@V run on tensor cores (tf32 wmma m16n16k8); softmax/decay in regs.
__global__ __launch_bounds__(256, 2)
void attn_kernel(const float* __restrict__ gammas)
{
    const int tid = threadIdx.x, lane = tid & 31, w = tid >> 5;
    const int bx = blockIdx.x, h = blockIdx.y, b = blockIdx.z;
    const int r0 = bx * 16 + 2 * w;
    const int r1 = r0 + 1;
    const int ntiles = (bx * 16 + 143) >> 7;         // key tiles of 128 needed
    const int bh = (b * 8 + h) * (1024 * 64);
    const float* qb = g_qh + bh;
    const float* kb = g_kh + bh;
    const float* vb = g_vh + bh;

    __shared__ float Qs[16][KV_LD];                  // Q tile  [row][d]
    __shared__ float KVs[128][KV_LD];                // K or V tile [j][d]
    __shared__ float Stg[16 * ST_LD];                // score/P stage; reused as O buf

    {
        const int r = tid >> 4, d4 = (tid & 15) << 2;
        const float4 qv = *(const float4*)&qb[(bx * 16 + r) * 64 + d4];
        Qs[r][d4] = qv.x; Qs[r][d4 + 1] = qv.y;
        Qs[r][d4 + 2] = qv.z; Qs[r][d4 + 3] = qv.w;
    }

    const float gx = gammas[h];
    const float gamma = -((gx > 20.f) ? gx : log1pf(expf(gx)));  // -softplus

    float s0[32], s1[32];

    // ---- Phase 1: scores C[16 x 128] per tile via tf32 wmma ----
    // warp w computes the n-subtile j_local in [w*16, w*16+16)
    for (int kt = 0; kt < ntiles; kt++) {
        float4 kv[2];
        {
            const int fi0 = tid, fi1 = tid + 256;
            kv[0] = *(const float4*)&kb[(kt * 128 + (fi0 >> 1)) * 64 + ((fi0 & 1) << 5)];
            kv[1] = *(const float4*)&kb[(kt * 128 + (fi1 >> 1)) * 64 + ((fi1 & 1) << 5)];
        }
        // second half of each 32-float chunk
        float4 kv2[2];
        {
            const int fi0 = tid, fi1 = tid + 256;
            kv2[0] = *(const float4*)&kb[(kt * 128 + (fi0 >> 1)) * 64 + ((fi0 & 1) << 5) + 4];
            kv2[1] = *(const float4*)&kb[(kt * 128 + (fi1 >> 1)) * 64 + ((fi1 & 1) << 5) + 4];
        }
        // ...plus remaining 24 floats per row handled by a simple strided copy:
        __syncthreads();   // previous tile's Stg reads + KVs use complete
        {
            // full copy: 128 rows x 64 floats, 8 float4 per thread
#pragma unroll
            for (int r = 0; r < 8; r++) {
                const int fi = tid + r * 256;
                const int jj = fi >> 4, d4 = (fi & 15) << 2;
                const float4 t4 = *(const float4*)&kb[(kt * 128 + jj) * 64 + d4];
                KVs[jj][d4] = t4.x; KVs[jj][d4 + 1] = t4.y;
                KVs[jj][d4 + 2] = t4.z; KVs[jj][d4 + 3] = t4.w;
            }
        }
        (void)kv; (void)kv2;
        __syncthreads();

        wmma::fragment<wmma::accumulator, 16, 16, 8, float> fc;
        wmma::fill_fragment(fc, 0.f);
#pragma unroll
        for (int kk = 0; kk < 8; kk++) {
            wmma::fragment<wmma::matrix_a, 16, 16, 8, wmma::precision::tf32, wmma::row_major> fa;
            wmma::fragment<wmma::matrix_b, 16, 16, 8, wmma::precision::tf32, wmma::col_major> fb;
            wmma::load_matrix_sync(fa, &Qs[0][kk * 8], KV_LD);
            wmma::load_matrix_sync(fb, &KVs[w * 16][kk * 8], KV_LD);
#pragma unroll
            for (int t = 0; t < fa.num_elements; t++) fa.x[t] = wmma::__float_to_tf32(fa.x[t]);
#pragma unroll
            for (int t = 0; t < fb.num_elements; t++) fb.x[t] = wmma::__float_to_tf32(fb.x[t]);
            wmma::mma_sync(fc, fa, fb, fc);
        }
        wmma::store_matrix_sync(&Stg[w * 16], fc, ST_LD, wmma::mem_row_major);
        __syncthreads();

        // pull this warp's 2 rows into the register j-map
#pragma unroll
        for (int t = 0; t < 4; t++) {
            s0[kt * 4 + t] = Stg[(2 * w) * ST_LD + t * 32 + lane];
            s1[kt * 4 + t] = Stg[(2 * w + 1) * ST_LD + t * 32 + lane];
        }
    }

    // ---- Phase 2: per-row softmax/decay/softmax (register machinery) ----
    const int nreg = ntiles * 4;
    row_decay_softmax(s0, r0, nreg, lane, gamma);
    row_decay_softmax(s1, r1, nreg, lane, gamma);

    // ---- Phase 3: O[16 x 64] += P[16 x 128] @ V[128 x 64] via tf32 wmma ----
    // warp w: n-subtile n0 = (w&3)*16, k-half = w>>2 (khalf*64 .. +64)
    const int n0 = (w & 3) * 16;
    const int khalf = w >> 2;
    wmma::fragment<wmma::accumulator, 16, 16, 8, float> facc;
    wmma::fill_fragment(facc, 0.f);

    for (int kt = 0; kt < ntiles; kt++) {
        __syncthreads();   // previous mma done with Stg/KVs
        // stage P for this tile + load V tile
#pragma unroll
        for (int t = 0; t < 4; t++) {
            Stg[(2 * w) * ST_LD + t * 32 + lane]     = s0[kt * 4 + t];
            Stg[(2 * w + 1) * ST_LD + t * 32 + lane] = s1[kt * 4 + t];
        }
#pragma unroll
        for (int r = 0; r < 8; r++) {
            const int fi = tid + r * 256;
            const int jj = fi >> 4, d4 = (fi & 15) << 2;
            const float4 t4 = *(const float4*)&vb[(kt * 128 + jj) * 64 + d4];
            KVs[jj][d4] = t4.x; KVs[jj][d4 + 1] = t4.y;
            KVs[jj][d4 + 2] = t4.z; KVs[jj][d4 + 3] = t4.w;
        }
        __syncthreads();

#pragma unroll
        for (int kk = 0; kk < 8; kk++) {
            const int k0 = khalf * 64 + kk * 8;
            wmma::fragment<wmma::matrix_a, 16, 16, 8, wmma::precision::tf32, wmma::row_major> pa;
            wmma::fragment<wmma::matrix_b, 16, 16, 8, wmma::precision::tf32, wmma::row_major> vbf;
            wmma::load_matrix_sync(pa, &Stg[k0], ST_LD);
            wmma::load_matrix_sync(vbf, &KVs[k0][n0], KV_LD);
#pragma unroll
            for (int t = 0; t < pa.num_elements; t++) pa.x[t] = wmma::__float_to_tf32(pa.x[t]);
#pragma unroll
            for (int t = 0; t < vbf.num_elements; t++) vbf.x[t] = wmma::__float_to_tf32(vbf.x[t]);
            wmma::mma_sync(facc, pa, vbf, facc);
        }
    }

    // combine the two k-halves: store to Stg (reused as O buffer [2][16][64])
    __syncthreads();
    wmma::store_matrix_sync(&Stg[khalf * 1024 + n0], facc, 64, wmma::mem_row_major);
    __syncthreads();

    {
        const int row = tid >> 4, d4 = (tid & 15) << 2;
        float4 o;
        o.x = Stg[row * 64 + d4]     + Stg[1024 + row * 64 + d4];
        o.y = Stg[row * 64 + d4 + 1] + Stg[1024 + row * 64 + d4 + 1];
        o.z = Stg[row * 64 + d4 + 2] + Stg[1024 + row * 64 + d4 + 2];
        o.w = Stg[row * 64 + d4 + 3] + Stg[1024 + row * 64 + d4 + 3];
        *(float4*)&g_ao[(b * 1024 + bx * 16 + row) * 512 + h * 64 + d4] = o;
    }
}

// ---------------- launch ----------------------------------------------------
extern "C" void kernel_launch(void* const* d_in, const int* in_sizes, int n_in,
                              void* d_out, int out_size)
{
    (void)in_sizes; (void)n_in; (void)out_size;
    const float* q  = (const float*)d_in[0];
    const float* k  = (const float*)d_in[1];
    const float* v  = (const float*)d_in[2];
    const float* Wk = (const float*)d_in[3];
    const float* bk = (const float*)d_in[4];
    const float* Wv = (const float*)d_in[5];
    const float* bv = (const float*)d_in[6];
    const float* Wo = (const float*)d_in[7];
    const float* bo = (const float*)d_in[8];
    const float* gm = (const float*)d_in[9];
    float* out = (float*)d_out;

    sgemm_nt<<<dim3(128, 4), 256>>>(q, k, Wk, bk, nullptr, 0);       // q,k -> g_qh,g_kh
    sgemm_nt<<<dim3(64, 4), 256>>>(v, nullptr, Wv, bv, nullptr, 2);  // -> g_vh

    attn_kernel<<<dim3(64, 8, 8), 256>>>(gm);                        // -> g_ao

    sgemm_nt<<<dim3(64, 4), 256>>>(nullptr, nullptr, Wo, bo, out, 3); // -> d_out
}

// round 7
// speedup vs baseline: 1.4966x; 1.1326x over previous
#include <cuda_runtime.h>
#include <math.h>
#include <mma.h>

using namespace nvcuda;

#define FULLMASK 0xffffffffu

#define BB 8
#define SS 1024
#define EE 512
#define HH 8
#define DD 64

// ---------------- scratch (device globals: allocation-free) ----------------
__device__ float g_qh[BB * HH * SS * DD];   // [b][h][s][d]
__device__ float g_kh[BB * HH * SS * DD];
__device__ float g_vh[BB * HH * SS * DD];
__device__ float g_ao[BB * SS * EE];        // attention output, [b][s][h*64+d]

// ---------------- tf32 WMMA projection: dst = A @ W^T + bias ---------------
// Block tile 128(M) x 64(N), K chunks of 32. 256 threads = 8 warps (4x2),
// warp tile 32x32 (2x2 m16n16k8 frags). Epilogue stages C in smem, then
// writes remapped [b][h][s][d] with fused bias (N-tile is 64-aligned so the
// head index is constant per block and d == tile column).
// mode 0: fused QK. grid.x=128: bx<64 -> A(q)->g_qh, bx>=64 -> A2(k)->g_kh
// mode 2: V -> g_vh (grid.x=64)
#define ALD 36   // A tile leading dim (128x32 + pad)
#define BLD 68   // B tile leading dim (32x64 + pad)
#define CLD 68   // C stage leading dim

__global__ __launch_bounds__(256, 2)
void proj_tf32(const float* __restrict__ A_param, const float* __restrict__ A2_param,
               const float* __restrict__ W, const float* __restrict__ bias,
               int mode)
{
    __shared__ __align__(16) float smem[128 * CLD];   // max(As+Bs, Cs)
    float* As = smem;                                  // [128][ALD]
    float* Bs = smem + 128 * ALD;                      // [32][BLD]
    float* Cs = smem;                                  // [128][CLD] (epilogue)

    int bxm = blockIdx.x;
    const float* A;
    float* dst;
    if (mode == 0) {
        if (bxm < 64) { A = A_param; dst = g_qh; }
        else          { A = A2_param; dst = g_kh; bxm -= 64; }
    } else {
        A = A_param; dst = g_vh;
    }

    const int tid = threadIdx.x;
    const int w = tid >> 5;
    const int wm = w >> 1;            // 0..3 -> M offset wm*32
    const int wn = w & 1;             // 0..1 -> N offset wn*32
    const int m0 = bxm * 128;
    const int n0 = blockIdx.y * 64;

    wmma::fragment<wmma::accumulator, 16, 16, 8, float> acc[2][2];
#pragma unroll
    for (int i = 0; i < 2; i++)
#pragma unroll
        for (int j = 0; j < 2; j++) wmma::fill_fragment(acc[i][j], 0.f);

    for (int k0 = 0; k0 < 512; k0 += 32) {
        __syncthreads();
#pragma unroll
        for (int i = 0; i < 4; i++) {                 // A: 128x32
            const int fi = tid + i * 256;
            const int r = fi >> 3, c4 = (fi & 7) << 2;
            *(float4*)&As[r * ALD + c4] =
                *(const float4*)&A[(m0 + r) * 512 + k0 + c4];
        }
#pragma unroll
        for (int i = 0; i < 2; i++) {                 // B: W[n][k] -> Bs[k][n]
            const int fi = tid + i * 256;
            const int n = fi >> 3, k4 = (fi & 7) << 2;
            const float4 w4 = *(const float4*)&W[(n0 + n) * 512 + k0 + k4];
            Bs[(k4 + 0) * BLD + n] = w4.x;
            Bs[(k4 + 1) * BLD + n] = w4.y;
            Bs[(k4 + 2) * BLD + n] = w4.z;
            Bs[(k4 + 3) * BLD + n] = w4.w;
        }
        __syncthreads();

#pragma unroll
        for (int ks = 0; ks < 4; ks++) {
            wmma::fragment<wmma::matrix_a, 16, 16, 8, wmma::precision::tf32, wmma::row_major> fa[2];
            wmma::fragment<wmma::matrix_b, 16, 16, 8, wmma::precision::tf32, wmma::row_major> fb[2];
#pragma unroll
            for (int i = 0; i < 2; i++) {
                wmma::load_matrix_sync(fa[i], &As[(wm * 32 + i * 16) * ALD + ks * 8], ALD);
#pragma unroll
                for (int t = 0; t < fa[i].num_elements; t++)
                    fa[i].x[t] = wmma::__float_to_tf32(fa[i].x[t]);
            }
#pragma unroll
            for (int j = 0; j < 2; j++) {
                wmma::load_matrix_sync(fb[j], &Bs[(ks * 8) * BLD + wn * 32 + j * 16], BLD);
#pragma unroll
                for (int t = 0; t < fb[j].num_elements; t++)
                    fb[j].x[t] = wmma::__float_to_tf32(fb[j].x[t]);
            }
#pragma unroll
            for (int i = 0; i < 2; i++)
#pragma unroll
                for (int j = 0; j < 2; j++)
                    wmma::mma_sync(acc[i][j], fa[i], fb[j], acc[i][j]);
        }
    }

    __syncthreads();
#pragma unroll
    for (int i = 0; i < 2; i++)
#pragma unroll
        for (int j = 0; j < 2; j++)
            wmma::store_matrix_sync(&Cs[(wm * 32 + i * 16) * CLD + wn * 32 + j * 16],
                                    acc[i][j], CLD, wmma::mem_row_major);
    __syncthreads();

    // epilogue: remap (m, n) -> [b][h][s][d]; hh const per block, d = col
    const int hh = n0 >> 6;
#pragma unroll
    for (int i = 0; i < 8; i++) {                     // 128x64 / 256 thr / 4
        const int fi = tid + i * 256;
        const int r = fi >> 4, c4 = (fi & 15) << 2;
        const int m = m0 + r;
        const int b = m >> 10, s = m & 1023;
        float4 o;
        o.x = Cs[r * CLD + c4 + 0] + bias[n0 + c4 + 0];
        o.y = Cs[r * CLD + c4 + 1] + bias[n0 + c4 + 1];
        o.z = Cs[r * CLD + c4 + 2] + bias[n0 + c4 + 2];
        o.w = Cs[r * CLD + c4 + 3] + bias[n0 + c4 + 3];
        *(float4*)&dst[(((b << 3) + hh) * 1024 + s) * 64 + c4] = o;
    }
}

// ---------------- scalar SGEMM (output projection only, fp32-exact) --------
__global__ __launch_bounds__(256, 2)
void sgemm_out(const float* __restrict__ W, const float* __restrict__ bias,
               float* __restrict__ C_param)
{
    __shared__ float As[8][128];
    __shared__ float Bs[8][128];

    const float* A = (const float*)g_ao;
    const int tid = threadIdx.x;
    const int m0 = blockIdx.x * 128;
    const int n0 = blockIdx.y * 128;
    const int ty = tid >> 4;
    const int tx = tid & 15;
    const int lr = tid >> 1;
    const int lc = (tid & 1) << 2;

    const float* Ap = A + (m0 + lr) * 512 + lc;
    const float* Wp = W + (n0 + lr) * 512 + lc;

    float acc[8][8];
#pragma unroll
    for (int i = 0; i < 8; i++)
#pragma unroll
        for (int j = 0; j < 8; j++) acc[i][j] = 0.f;

    for (int k0 = 0; k0 < 512; k0 += 8) {
        float4 av = *(const float4*)(Ap + k0);
        float4 wv = *(const float4*)(Wp + k0);
        __syncthreads();
        As[lc + 0][lr] = av.x; As[lc + 1][lr] = av.y;
        As[lc + 2][lr] = av.z; As[lc + 3][lr] = av.w;
        Bs[lc + 0][lr] = wv.x; Bs[lc + 1][lr] = wv.y;
        Bs[lc + 2][lr] = wv.z; Bs[lc + 3][lr] = wv.w;
        __syncthreads();
#pragma unroll
        for (int kk = 0; kk < 8; kk++) {
            float a[8], bb[8];
            *(float4*)(a)      = *(const float4*)&As[kk][ty * 8];
            *(float4*)(a + 4)  = *(const float4*)&As[kk][ty * 8 + 4];
            *(float4*)(bb)     = *(const float4*)&Bs[kk][tx * 8];
            *(float4*)(bb + 4) = *(const float4*)&Bs[kk][tx * 8 + 4];
#pragma unroll
            for (int i = 0; i < 8; i++)
#pragma unroll
                for (int j = 0; j < 8; j++)
                    acc[i][j] = fmaf(a[i], bb[j], acc[i][j]);
        }
    }

#pragma unroll
    for (int i = 0; i < 8; i++) {
        const int m = m0 + ty * 8 + i;
#pragma unroll
        for (int j = 0; j < 8; j++) {
            const int n = n0 + tx * 8 + j;
            C_param[m * 512 + n] = acc[i][j] + bias[n];
        }
    }
}

// ---------------- fused decay-attention ------------------------------------
__device__ __forceinline__ float wredmax(float v) {
#pragma unroll
    for (int o = 16; o; o >>= 1) v = fmaxf(v, __shfl_xor_sync(FULLMASK, v, o));
    return v;
}
__device__ __forceinline__ float wredsum(float v) {
#pragma unroll
    for (int o = 16; o; o >>= 1) v += __shfl_xor_sync(FULLMASK, v, o);
    return v;
}

// softmax -> cumsum decay -> rescaled softmax, entirely in registers.
// j-map: j = (c>>2)*128 + (c&3)*32 + lane
__device__ __forceinline__ void row_decay_softmax(float (&s)[32], const int i,
                                                  const int nreg, const int lane,
                                                  const float gamma)
{
    float m1 = -3.0e38f;
#pragma unroll
    for (int c = 0; c < 32; c++) if (c < nreg) {
        const int j = (c >> 2) * 128 + (c & 3) * 32 + lane;
        s[c] *= 0.125f;                              // 1/sqrt(64)
        if (j <= i) m1 = fmaxf(m1, s[c]);
    }
    m1 = wredmax(m1);

    float Z = 0.f;
#pragma unroll
    for (int c = 0; c < 32; c++) if (c < nreg) {
        const int j = (c >> 2) * 128 + (c & 3) * 32 + lane;
        if (j <= i) Z += __expf(s[c] - m1);
    }
    Z = wredsum(Z);
    const float invZ = 1.f / Z;

    float carry = 0.f;
#pragma unroll
    for (int c = 0; c < 32; c++) if (c < nreg) {
        const int j = (c >> 2) * 128 + (c & 3) * 32 + lane;
        float v = (j <= i) ? __expf(s[c] - m1) * invZ : 0.f;
#pragma unroll
        for (int o = 1; o < 32; o <<= 1) {
            const float n = __shfl_up_sync(FULLMASK, v, o);
            if (lane >= o) v += n;
        }
        const float cum = carry + v;
        carry = __shfl_sync(FULLMASK, cum, 31);
        float x = fmaxf((1.f - cum) * (float)(i - j), 0.f);
        float eff = __expf(sqrtf(x) * gamma);
        eff = fminf(fmaxf(eff, 1e-5f), 1e5f);
        s[c] *= eff;
    }

    float m2 = -3.0e38f;
#pragma unroll
    for (int c = 0; c < 32; c++) if (c < nreg) {
        const int j = (c >> 2) * 128 + (c & 3) * 32 + lane;
        if (j <= i) m2 = fmaxf(m2, s[c]);
    }
    m2 = wredmax(m2);

    float Z2 = 0.f;
#pragma unroll
    for (int c = 0; c < 32; c++) {
        if (c < nreg) {
            const int j = (c >> 2) * 128 + (c & 3) * 32 + lane;
            s[c] = (j <= i) ? __expf(s[c] - m2) : 0.f;
            Z2 += s[c];
        } else s[c] = 0.f;
    }
    Z2 = wredsum(Z2);
    const float psc = (i == 0) ? 0.f : (1.f / Z2);
#pragma unroll
    for (int c = 0; c < 32; c++) s[c] *= psc;
}

#define KV_LD 68     // padded leading dim for K/V tile
#define ST_LD 136    // padded leading dim for stage buffer

// grid (64, H, B), 256 threads: 8 warps, block covers 16 query rows.
__global__ __launch_bounds__(256, 2)
void attn_kernel(const float* __restrict__ gammas)
{
    const int tid = threadIdx.x, lane = tid & 31, w = tid >> 5;
    const int bx = blockIdx.x, h = blockIdx.y, b = blockIdx.z;
    const int r0 = bx * 16 + 2 * w;
    const int r1 = r0 + 1;
    const int ntiles = (bx * 16 + 143) >> 7;
    const int bh = (b * 8 + h) * (1024 * 64);
    const float* qb = g_qh + bh;
    const float* kb = g_kh + bh;
    const float* vb = g_vh + bh;

    __shared__ float Qs[16][KV_LD];
    __shared__ float KVs[128][KV_LD];
    __shared__ float Stg[16 * ST_LD];

    {
        const int r = tid >> 4, d4 = (tid & 15) << 2;
        const float4 qv = *(const float4*)&qb[(bx * 16 + r) * 64 + d4];
        Qs[r][d4] = qv.x; Qs[r][d4 + 1] = qv.y;
        Qs[r][d4 + 2] = qv.z; Qs[r][d4 + 3] = qv.w;
    }

    const float gx = gammas[h];
    const float gamma = -((gx > 20.f) ? gx : log1pf(expf(gx)));

    float s0[32], s1[32];

    // ---- Phase 1: scores C[16 x 128] per tile via tf32 wmma ----
    for (int kt = 0; kt < ntiles; kt++) {
        __syncthreads();
#pragma unroll
        for (int r = 0; r < 8; r++) {
            const int fi = tid + r * 256;
            const int jj = fi >> 4, d4 = (fi & 15) << 2;
            const float4 t4 = *(const float4*)&kb[(kt * 128 + jj) * 64 + d4];
            KVs[jj][d4] = t4.x; KVs[jj][d4 + 1] = t4.y;
            KVs[jj][d4 + 2] = t4.z; KVs[jj][d4 + 3] = t4.w;
        }
        __syncthreads();

        wmma::fragment<wmma::accumulator, 16, 16, 8, float> fc;
        wmma::fill_fragment(fc, 0.f);
#pragma unroll
        for (int kk = 0; kk < 8; kk++) {
            wmma::fragment<wmma::matrix_a, 16, 16, 8, wmma::precision::tf32, wmma::row_major> fa;
            wmma::fragment<wmma::matrix_b, 16, 16, 8, wmma::precision::tf32, wmma::col_major> fb;
            wmma::load_matrix_sync(fa, &Qs[0][kk * 8], KV_LD);
            wmma::load_matrix_sync(fb, &KVs[w * 16][kk * 8], KV_LD);
#pragma unroll
            for (int t = 0; t < fa.num_elements; t++) fa.x[t] = wmma::__float_to_tf32(fa.x[t]);
#pragma unroll
            for (int t = 0; t < fb.num_elements; t++) fb.x[t] = wmma::__float_to_tf32(fb.x[t]);
            wmma::mma_sync(fc, fa, fb, fc);
        }
        wmma::store_matrix_sync(&Stg[w * 16], fc, ST_LD, wmma::mem_row_major);
        __syncthreads();

#pragma unroll
        for (int t = 0; t < 4; t++) {
            s0[kt * 4 + t] = Stg[(2 * w) * ST_LD + t * 32 + lane];
            s1[kt * 4 + t] = Stg[(2 * w + 1) * ST_LD + t * 32 + lane];
        }
    }

    // ---- Phase 2: per-row softmax/decay/softmax ----
    const int nreg = ntiles * 4;
    row_decay_softmax(s0, r0, nreg, lane, gamma);
    row_decay_softmax(s1, r1, nreg, lane, gamma);

    // ---- Phase 3: O[16 x 64] = P @ V via tf32 wmma ----
    const int n0 = (w & 3) * 16;
    const int khalf = w >> 2;
    wmma::fragment<wmma::accumulator, 16, 16, 8, float> facc;
    wmma::fill_fragment(facc, 0.f);

    for (int kt = 0; kt < ntiles; kt++) {
        __syncthreads();
#pragma unroll
        for (int t = 0; t < 4; t++) {
            Stg[(2 * w) * ST_LD + t * 32 + lane]     = s0[kt * 4 + t];
            Stg[(2 * w + 1) * ST_LD + t * 32 + lane] = s1[kt * 4 + t];
        }
#pragma unroll
        for (int r = 0; r < 8; r++) {
            const int fi = tid + r * 256;
            const int jj = fi >> 4, d4 = (fi & 15) << 2;
            const float4 t4 = *(const float4*)&vb[(kt * 128 + jj) * 64 + d4];
            KVs[jj][d4] = t4.x; KVs[jj][d4 + 1] = t4.y;
            KVs[jj][d4 + 2] = t4.z; KVs[jj][d4 + 3] = t4.w;
        }
        __syncthreads();

#pragma unroll
        for (int kk = 0; kk < 8; kk++) {
            const int k0 = khalf * 64 + kk * 8;
            wmma::fragment<wmma::matrix_a, 16, 16, 8, wmma::precision::tf32, wmma::row_major> pa;
            wmma::fragment<wmma::matrix_b, 16, 16, 8, wmma::precision::tf32, wmma::row_major> vbf;
            wmma::load_matrix_sync(pa, &Stg[k0], ST_LD);
            wmma::load_matrix_sync(vbf, &KVs[k0][n0], KV_LD);
#pragma unroll
            for (int t = 0; t < pa.num_elements; t++) pa.x[t] = wmma::__float_to_tf32(pa.x[t]);
#pragma unroll
            for (int t = 0; t < vbf.num_elements; t++) vbf.x[t] = wmma::__float_to_tf32(vbf.x[t]);
            wmma::mma_sync(facc, pa, vbf, facc);
        }
    }

    __syncthreads();
    wmma::store_matrix_sync(&Stg[khalf * 1024 + n0], facc, 64, wmma::mem_row_major);
    __syncthreads();

    {
        const int row = tid >> 4, d4 = (tid & 15) << 2;
        float4 o;
        o.x = Stg[row * 64 + d4]     + Stg[1024 + row * 64 + d4];
        o.y = Stg[row * 64 + d4 + 1] + Stg[1024 + row * 64 + d4 + 1];
        o.z = Stg[row * 64 + d4 + 2] + Stg[1024 + row * 64 + d4 + 2];
        o.w = Stg[row * 64 + d4 + 3] + Stg[1024 + row * 64 + d4 + 3];
        *(float4*)&g_ao[(b * 1024 + bx * 16 + row) * 512 + h * 64 + d4] = o;
    }
}

// ---------------- launch ----------------------------------------------------
extern "C" void kernel_launch(void* const* d_in, const int* in_sizes, int n_in,
                              void* d_out, int out_size)
{
    (void)in_sizes; (void)n_in; (void)out_size;
    const float* q  = (const float*)d_in[0];
    const float* k  = (const float*)d_in[1];
    const float* v  = (const float*)d_in[2];
    const float* Wk = (const float*)d_in[3];
    const float* bk = (const float*)d_in[4];
    const float* Wv = (const float*)d_in[5];
    const float* bv = (const float*)d_in[6];
    const float* Wo = (const float*)d_in[7];
    const float* bo = (const float*)d_in[8];
    const float* gm = (const float*)d_in[9];
    float* out = (float*)d_out;

    proj_tf32<<<dim3(128, 8), 256>>>(q, k, Wk, bk, 0);       // q,k -> g_qh,g_kh
    proj_tf32<<<dim3(64, 8), 256>>>(v, nullptr, Wv, bv, 2);  // -> g_vh

    attn_kernel<<<dim3(64, 8, 8), 256>>>(gm);                // -> g_ao

    sgemm_out<<<dim3(64, 4), 256>>>(Wo, bo, out);            // g_ao -> d_out (fp32)
}

// round 9
// speedup vs baseline: 1.6038x; 1.0716x over previous
#include <cuda_runtime.h>
#include <math.h>
#include <mma.h>

using namespace nvcuda;

#define FULLMASK 0xffffffffu

#define BB 8
#define SS 1024
#define EE 512
#define HH 8
#define DD 64

// ---------------- scratch (device globals: allocation-free) ----------------
__device__ float g_qh[BB * HH * SS * DD];   // [b][h][s][d]
__device__ float g_kh[BB * HH * SS * DD];
__device__ float g_vh[BB * HH * SS * DD];
__device__ float g_ao[BB * SS * EE];        // attention output, [b][s][h*64+d]

// ---------------- tf32 WMMA projection: dst = A @ W^T + bias ---------------
// Block tile 128(M) x 64(N), K chunks of 32. 256 threads = 8 warps (4x2).
// mode 0: fused QK. grid.x=128: bx<64 -> A(q)->g_qh, bx>=64 -> A2(k)->g_kh
// mode 2: V -> g_vh (grid.x=64)
// mode 3: out-proj: g_ao @ W^T + bias -> C_param[m*512+n] (grid.x=64)
#define ALD 36   // A tile leading dim (128x32 + pad)
#define BLD 68   // B tile leading dim (32x64 + pad)
#define CLD 68   // C stage leading dim

__global__ __launch_bounds__(256, 2)
void proj_tf32(const float* __restrict__ A_param, const float* __restrict__ A2_param,
               const float* __restrict__ W, const float* __restrict__ bias,
               float* __restrict__ C_param, int mode)
{
    __shared__ __align__(16) float smem[128 * CLD];   // max(As+Bs, Cs)
    float* As = smem;                                  // [128][ALD]
    float* Bs = smem + 128 * ALD;                      // [32][BLD]
    float* Cs = smem;                                  // [128][CLD] (epilogue)

    int bxm = blockIdx.x;
    const float* A;
    float* dst = nullptr;
    if (mode == 0) {
        if (bxm < 64) { A = A_param; dst = g_qh; }
        else          { A = A2_param; dst = g_kh; bxm -= 64; }
    } else if (mode == 2) {
        A = A_param; dst = g_vh;
    } else {
        A = (const float*)g_ao;
    }

    const int tid = threadIdx.x;
    const int w = tid >> 5;
    const int wm = w >> 1;            // 0..3 -> M offset wm*32
    const int wn = w & 1;             // 0..1 -> N offset wn*32
    const int m0 = bxm * 128;
    const int n0 = blockIdx.y * 64;

    wmma::fragment<wmma::accumulator, 16, 16, 8, float> acc[2][2];
#pragma unroll
    for (int i = 0; i < 2; i++)
#pragma unroll
        for (int j = 0; j < 2; j++) wmma::fill_fragment(acc[i][j], 0.f);

    for (int k0 = 0; k0 < 512; k0 += 32) {
        __syncthreads();
#pragma unroll
        for (int i = 0; i < 4; i++) {                 // A: 128x32
            const int fi = tid + i * 256;
            const int r = fi >> 3, c4 = (fi & 7) << 2;
            *(float4*)&As[r * ALD + c4] =
                *(const float4*)&A[(m0 + r) * 512 + k0 + c4];
        }
#pragma unroll
        for (int i = 0; i < 2; i++) {                 // B: W[n][k] -> Bs[k][n]
            const int fi = tid + i * 256;
            const int n = fi >> 3, k4 = (fi & 7) << 2;
            const float4 w4 = *(const float4*)&W[(n0 + n) * 512 + k0 + k4];
            Bs[(k4 + 0) * BLD + n] = w4.x;
            Bs[(k4 + 1) * BLD + n] = w4.y;
            Bs[(k4 + 2) * BLD + n] = w4.z;
            Bs[(k4 + 3) * BLD + n] = w4.w;
        }
        __syncthreads();

#pragma unroll
        for (int ks = 0; ks < 4; ks++) {
            wmma::fragment<wmma::matrix_a, 16, 16, 8, wmma::precision::tf32, wmma::row_major> fa[2];
            wmma::fragment<wmma::matrix_b, 16, 16, 8, wmma::precision::tf32, wmma::row_major> fb[2];
#pragma unroll
            for (int i = 0; i < 2; i++) {
                wmma::load_matrix_sync(fa[i], &As[(wm * 32 + i * 16) * ALD + ks * 8], ALD);
#pragma unroll
                for (int t = 0; t < fa[i].num_elements; t++)
                    fa[i].x[t] = wmma::__float_to_tf32(fa[i].x[t]);
            }
#pragma unroll
            for (int j = 0; j < 2; j++) {
                wmma::load_matrix_sync(fb[j], &Bs[(ks * 8) * BLD + wn * 32 + j * 16], BLD);
#pragma unroll
                for (int t = 0; t < fb[j].num_elements; t++)
                    fb[j].x[t] = wmma::__float_to_tf32(fb[j].x[t]);
            }
#pragma unroll
            for (int i = 0; i < 2; i++)
#pragma unroll
                for (int j = 0; j < 2; j++)
                    wmma::mma_sync(acc[i][j], fa[i], fb[j], acc[i][j]);
        }
    }

    __syncthreads();
#pragma unroll
    for (int i = 0; i < 2; i++)
#pragma unroll
        for (int j = 0; j < 2; j++)
            wmma::store_matrix_sync(&Cs[(wm * 32 + i * 16) * CLD + wn * 32 + j * 16],
                                    acc[i][j], CLD, wmma::mem_row_major);
    __syncthreads();

    if (mode == 3) {
        // plain epilogue: C[m*512 + n] = Cs + bias
#pragma unroll
        for (int i = 0; i < 8; i++) {
            const int fi = tid + i * 256;
            const int r = fi >> 4, c4 = (fi & 15) << 2;
            const int m = m0 + r;
            float4 o;
            o.x = Cs[r * CLD + c4 + 0] + bias[n0 + c4 + 0];
            o.y = Cs[r * CLD + c4 + 1] + bias[n0 + c4 + 1];
            o.z = Cs[r * CLD + c4 + 2] + bias[n0 + c4 + 2];
            o.w = Cs[r * CLD + c4 + 3] + bias[n0 + c4 + 3];
            *(float4*)&C_param[m * 512 + n0 + c4] = o;
        }
    } else {
        // remap (m, n) -> [b][h][s][d]; hh const per block, d = col
        const int hh = n0 >> 6;
#pragma unroll
        for (int i = 0; i < 8; i++) {
            const int fi = tid + i * 256;
            const int r = fi >> 4, c4 = (fi & 15) << 2;
            const int m = m0 + r;
            const int b = m >> 10, s = m & 1023;
            float4 o;
            o.x = Cs[r * CLD + c4 + 0] + bias[n0 + c4 + 0];
            o.y = Cs[r * CLD + c4 + 1] + bias[n0 + c4 + 1];
            o.z = Cs[r * CLD + c4 + 2] + bias[n0 + c4 + 2];
            o.w = Cs[r * CLD + c4 + 3] + bias[n0 + c4 + 3];
            *(float4*)&dst[(((b << 3) + hh) * 1024 + s) * 64 + c4] = o;
        }
    }
}

// ---------------- fused decay-attention ------------------------------------
__device__ __forceinline__ float wredmax(float v) {
#pragma unroll
    for (int o = 16; o; o >>= 1) v = fmaxf(v, __shfl_xor_sync(FULLMASK, v, o));
    return v;
}
__device__ __forceinline__ float wredsum(float v) {
#pragma unroll
    for (int o = 16; o; o >>= 1) v += __shfl_xor_sync(FULLMASK, v, o);
    return v;
}

// softmax -> cumsum decay -> rescaled softmax, entirely in registers.
// j-map: j = (c>>2)*128 + (c&3)*32 + lane
// 3 exps/element: scan computes unnormalized cumsum; its final carry == Z.
__device__ __forceinline__ void row_decay_softmax(float (&s)[32], const int i,
                                                  const int nreg, const int lane,
                                                  const float gamma)
{
    float m1 = -3.0e38f;
#pragma unroll
    for (int c = 0; c < 32; c++) if (c < nreg) {
        const int j = (c >> 2) * 128 + (c & 3) * 32 + lane;
        s[c] *= 0.125f;                              // 1/sqrt(64)
        if (j <= i) m1 = fmaxf(m1, s[c]);
    }
    m1 = wredmax(m1);

    // scan pass over unnormalized p = exp(s - m1); cum[] inclusive, carry -> Z
    float cum[32];
    float carry = 0.f;
#pragma unroll
    for (int c = 0; c < 32; c++) if (c < nreg) {
        const int j = (c >> 2) * 128 + (c & 3) * 32 + lane;
        float v = (j <= i) ? __expf(s[c] - m1) : 0.f;
#pragma unroll
        for (int o = 1; o < 32; o <<= 1) {
            const float n = __shfl_up_sync(FULLMASK, v, o);
            if (lane >= o) v += n;
        }
        cum[c] = carry + v;
        carry = __shfl_sync(FULLMASK, cum[c], 31);
    }
    const float invZ = 1.f / carry;                  // Z == final carry

    // decay pass (fused m2 tracking)
    float m2 = -3.0e38f;
#pragma unroll
    for (int c = 0; c < 32; c++) if (c < nreg) {
        const int j = (c >> 2) * 128 + (c & 3) * 32 + lane;
        float x = fmaxf((1.f - cum[c] * invZ) * (float)(i - j), 0.f);
        float eff = __expf(sqrtf(x) * gamma);
        eff = fminf(fmaxf(eff, 1e-5f), 1e5f);
        s[c] *= eff;
        if (j <= i) m2 = fmaxf(m2, s[c]);
    }
    m2 = wredmax(m2);

    float Z2 = 0.f;
#pragma unroll
    for (int c = 0; c < 32; c++) {
        if (c < nreg) {
            const int j = (c >> 2) * 128 + (c & 3) * 32 + lane;
            s[c] = (j <= i) ? __expf(s[c] - m2) : 0.f;
            Z2 += s[c];
        } else s[c] = 0.f;
    }
    Z2 = wredsum(Z2);
    const float psc = (i == 0) ? 0.f : (1.f / Z2);   // zero_pad first query row
#pragma unroll
    for (int c = 0; c < 32; c++) s[c] *= psc;
}

#define KV_LD 68     // padded leading dim for K/V tile
#define ST_LD 136    // padded leading dim for stage buffer

// grid (64, H, B), 256 threads: 8 warps, block covers 16 query rows.
__global__ __launch_bounds__(256, 2)
void attn_kernel(const float* __restrict__ gammas)
{
    const int tid = threadIdx.x, lane = tid & 31, w = tid >> 5;
    const int bx = blockIdx.x, h = blockIdx.y, b = blockIdx.z;
    const int r0 = bx * 16 + 2 * w;
    const int r1 = r0 + 1;
    const int ntiles = (bx * 16 + 143) >> 7;
    const int bh = (b * 8 + h) * (1024 * 64);
    const float* qb = g_qh + bh;
    const float* kb = g_kh + bh;
    const float* vb = g_vh + bh;

    __shared__ float Qs[16][KV_LD];
    __shared__ float KVs[128][KV_LD];
    __shared__ float Stg[16 * ST_LD];

    {
        const int r = tid >> 4, d4 = (tid & 15) << 2;
        const float4 qv = *(const float4*)&qb[(bx * 16 + r) * 64 + d4];
        Qs[r][d4] = qv.x; Qs[r][d4 + 1] = qv.y;
        Qs[r][d4 + 2] = qv.z; Qs[r][d4 + 3] = qv.w;
    }

    const float gx = gammas[h];
    const float gamma = -((gx > 20.f) ? gx : log1pf(expf(gx)));

    float s0[32], s1[32];

    // ---- Phase 1: scores C[16 x 128] per tile via tf32 wmma ----
    for (int kt = 0; kt < ntiles; kt++) {
        __syncthreads();
#pragma unroll
        for (int r = 0; r < 8; r++) {
            const int fi = tid + r * 256;
            const int jj = fi >> 4, d4 = (fi & 15) << 2;
            const float4 t4 = *(const float4*)&kb[(kt * 128 + jj) * 64 + d4];
            KVs[jj][d4] = t4.x; KVs[jj][d4 + 1] = t4.y;
            KVs[jj][d4 + 2] = t4.z; KVs[jj][d4 + 3] = t4.w;
        }
        __syncthreads();

        wmma::fragment<wmma::accumulator, 16, 16, 8, float> fc;
        wmma::fill_fragment(fc, 0.f);
#pragma unroll
        for (int kk = 0; kk < 8; kk++) {
            wmma::fragment<wmma::matrix_a, 16, 16, 8, wmma::precision::tf32, wmma::row_major> fa;
            wmma::fragment<wmma::matrix_b, 16, 16, 8, wmma::precision::tf32, wmma::col_major> fb;
            wmma::load_matrix_sync(fa, &Qs[0][kk * 8], KV_LD);
            wmma::load_matrix_sync(fb, &KVs[w * 16][kk * 8], KV_LD);
#pragma unroll
            for (int t = 0; t < fa.num_elements; t++) fa.x[t] = wmma::__float_to_tf32(fa.x[t]);
#pragma unroll
            for (int t = 0; t < fb.num_elements; t++) fb.x[t] = wmma::__float_to_tf32(fb.x[t]);
            wmma::mma_sync(fc, fa, fb, fc);
        }
        wmma::store_matrix_sync(&Stg[w * 16], fc, ST_LD, wmma::mem_row_major);
        __syncthreads();

#pragma unroll
        for (int t = 0; t < 4; t++) {
            s0[kt * 4 + t] = Stg[(2 * w) * ST_LD + t * 32 + lane];
            s1[kt * 4 + t] = Stg[(2 * w + 1) * ST_LD + t * 32 + lane];
        }
    }

    // ---- Phase 2: per-row softmax/decay/softmax ----
    const int nreg = ntiles * 4;
    row_decay_softmax(s0, r0, nreg, lane, gamma);
    row_decay_softmax(s1, r1, nreg, lane, gamma);

    // ---- Phase 3: O[16 x 64] = P @ V via tf32 wmma ----
    const int n0 = (w & 3) * 16;
    const int khalf = w >> 2;
    wmma::fragment<wmma::accumulator, 16, 16, 8, float> facc;
    wmma::fill_fragment(facc, 0.f);

    for (int kt = 0; kt < ntiles; kt++) {
        __syncthreads();
#pragma unroll
        for (int t = 0; t < 4; t++) {
            Stg[(2 * w) * ST_LD + t * 32 + lane]     = s0[kt * 4 + t];
            Stg[(2 * w + 1) * ST_LD + t * 32 + lane] = s1[kt * 4 + t];
        }
#pragma unroll
        for (int r = 0; r < 8; r++) {
            const int fi = tid + r * 256;
            const int jj = fi >> 4, d4 = (fi & 15) << 2;
            const float4 t4 = *(const float4*)&vb[(kt * 128 + jj) * 64 + d4];
            KVs[jj][d4] = t4.x; KVs[jj][d4 + 1] = t4.y;
            KVs[jj][d4 + 2] = t4.z; KVs[jj][d4 + 3] = t4.w;
        }
        __syncthreads();

#pragma unroll
        for (int kk = 0; kk < 8; kk++) {
            const int k0 = khalf * 64 + kk * 8;
            wmma::fragment<wmma::matrix_a, 16, 16, 8, wmma::precision::tf32, wmma::row_major> pa;
            wmma::fragment<wmma::matrix_b, 16, 16, 8, wmma::precision::tf32, wmma::row_major> vbf;
            wmma::load_matrix_sync(pa, &Stg[k0], ST_LD);
            wmma::load_matrix_sync(vbf, &KVs[k0][n0], KV_LD);
#pragma unroll
            for (int t = 0; t < pa.num_elements; t++) pa.x[t] = wmma::__float_to_tf32(pa.x[t]);
#pragma unroll
            for (int t = 0; t < vbf.num_elements; t++) vbf.x[t] = wmma::__float_to_tf32(vbf.x[t]);
            wmma::mma_sync(facc, pa, vbf, facc);
        }
    }

    __syncthreads();
    wmma::store_matrix_sync(&Stg[khalf * 1024 + n0], facc, 64, wmma::mem_row_major);
    __syncthreads();

    {
        const int row = tid >> 4, d4 = (tid & 15) << 2;
        float4 o;
        o.x = Stg[row * 64 + d4]     + Stg[1024 + row * 64 + d4];
        o.y = Stg[row * 64 + d4 + 1] + Stg[1024 + row * 64 + d4 + 1];
        o.z = Stg[row * 64 + d4 + 2] + Stg[1024 + row * 64 + d4 + 2];
        o.w = Stg[row * 64 + d4 + 3] + Stg[1024 + row * 64 + d4 + 3];
        *(float4*)&g_ao[(b * 1024 + bx * 16 + row) * 512 + h * 64 + d4] = o;
    }
}

// ---------------- launch ----------------------------------------------------
extern "C" void kernel_launch(void* const* d_in, const int* in_sizes, int n_in,
                              void* d_out, int out_size)
{
    (void)in_sizes; (void)n_in; (void)out_size;
    const float* q  = (const float*)d_in[0];
    const float* k  = (const float*)d_in[1];
    const float* v  = (const float*)d_in[2];
    const float* Wk = (const float*)d_in[3];
    const float* bk = (const float*)d_in[4];
    const float* Wv = (const float*)d_in[5];
    const float* bv = (const float*)d_in[6];
    const float* Wo = (const float*)d_in[7];
    const float* bo = (const float*)d_in[8];
    const float* gm = (const float*)d_in[9];
    float* out = (float*)d_out;

    proj_tf32<<<dim3(128, 8), 256>>>(q, k, Wk, bk, nullptr, 0);      // q,k -> g_qh,g_kh
    proj_tf32<<<dim3(64, 8), 256>>>(v, nullptr, Wv, bv, nullptr, 2); // -> g_vh

    attn_kernel<<<dim3(64, 8, 8), 256>>>(gm);                        // -> g_ao

    proj_tf32<<<dim3(64, 8), 256>>>(nullptr, nullptr, Wo, bo, out, 3); // -> d_out
}